// round 4
// baseline (speedup 1.0000x reference)
#include <cuda_runtime.h>
#include <cuda_bf16.h>
#include <stdint.h>
#include <math.h>

// ---------------------------------------------------------------------------
// QRNN on sm_103 (family target; tcgen05 unavailable in this harness).
// gates GEMM (M=32768, N=1536, K=1024) via mma.sync s8 two-limb fixed point:
//   x = 2^-11 (X1*128 + X0),  w = 2^-18 (W1*128 + W0)
//   gate = 2^-15*S(X1W1) + 2^-22*S(X1W0 + X0W1)   (X0W0 dropped, ~1e-4)
// then fo-pool chunked scan.
// ---------------------------------------------------------------------------

#define B_   8
#define T_   4096
#define D_   512
#define U_   512
#define N3_  1536
#define K_   1024
#define M_   (B_*T_)

#define BM 128
#define BN 128
#define BK 64                     // k-elems (bytes) per stage
#define KCHUNKS (K_/BK)           // 16
#define STAGES 4

#define ROWB        80            // 64 data bytes + 16 pad (conflict-free)
#define MAT_BYTES   (128*ROWB)                 // 10240
#define STAGE_BYTES (4*MAT_BYTES)              // 40960
#define SMEM_TOTAL  (STAGES*STAGE_BYTES)       // 163840

#define NCHUNK 32
#define TCHUNK (T_/NCHUNK)        // 128

// ---- scratch ----------------------------------------------------------------
__device__ float g_gates[(size_t)M_ * N3_];
__device__ float g_cend [B_*NCHUNK*U_];
__device__ float g_P    [B_*NCHUNK*U_];
__device__ float g_cst  [B_*NCHUNK*U_];
__device__ int8_t g_x1[(size_t)M_ * D_];
__device__ int8_t g_x0[(size_t)M_ * D_];
__device__ int8_t g_w1[(size_t)N3_ * K_];   // transposed [N,K]
__device__ int8_t g_w0[(size_t)N3_ * K_];

// ---- helpers ------------------------------------------------------------------
__device__ __forceinline__ uint32_t smem_u32(const void* p) {
    uint32_t r;
    asm("{ .reg .u64 t; cvta.to.shared.u64 t, %1; cvt.u32.u64 %0, t; }" : "=r"(r) : "l"(p));
    return r;
}
__device__ __forceinline__ void cp16(uint32_t dst, const void* src, int ssize) {
    asm volatile("cp.async.cg.shared.global [%0], [%1], 16, %2;"
                 :: "r"(dst), "l"(src), "r"(ssize) : "memory");
}
__device__ __forceinline__ void ldm_x4(uint32_t* r, uint32_t addr) {
    asm volatile("ldmatrix.sync.aligned.m8n8.x4.shared.b16 {%0,%1,%2,%3}, [%4];"
                 : "=r"(r[0]), "=r"(r[1]), "=r"(r[2]), "=r"(r[3]) : "r"(addr));
}
__device__ __forceinline__ void imma16832(int* d, const uint32_t* a,
                                          uint32_t b0, uint32_t b1) {
    asm volatile(
        "mma.sync.aligned.m16n8k32.row.col.s32.s8.s8.s32 "
        "{%0,%1,%2,%3},{%4,%5,%6,%7},{%8,%9},{%0,%1,%2,%3};"
        : "+r"(d[0]), "+r"(d[1]), "+r"(d[2]), "+r"(d[3])
        : "r"(a[0]), "r"(a[1]), "r"(a[2]), "r"(a[3]), "r"(b0), "r"(b1));
}
__device__ __forceinline__ float sigf(float x) {
    float e = __expf(-x);
    float d = 1.f + e, r;
    asm("rcp.approx.f32 %0, %1;" : "=f"(r) : "f"(d));
    return r;
}
__device__ __forceinline__ float tanhf_fast(float x) {
    return 2.f * sigf(2.f * x) - 1.f;
}
__device__ __forceinline__ void split_limbs(float v, float scale, int8_t& hi, int8_t& lo) {
    int q = __float2int_rn(v * scale);
    q = max(min(q, 16319), -16320);
    const int h = (q + 64) >> 7;
    hi = (int8_t)h;
    lo = (int8_t)(q - (h << 7));
}

// ---------------------------------------------------------------------------
// converters
// ---------------------------------------------------------------------------
__global__ __launch_bounds__(256) void convert_x(const float* __restrict__ x) {
    size_t i = ((size_t)blockIdx.x * blockDim.x + threadIdx.x) * 4;
    float4 v = *(const float4*)(x + i);
    float vv[4] = {v.x, v.y, v.z, v.w};
    int8_t h[4], l[4];
    #pragma unroll
    for (int j = 0; j < 4; j++) split_limbs(vv[j], 2048.f, h[j], l[j]);
    *(uint32_t*)(g_x1 + i) = *(uint32_t*)h;
    *(uint32_t*)(g_x0 + i) = *(uint32_t*)l;
}

__global__ __launch_bounds__(256) void convert_k(const float* __restrict__ kern) {
    int idx = blockIdx.x * blockDim.x + threadIdx.x;   // over N3_*K_
    int n = idx >> 10;
    int k = idx & (K_ - 1);
    int8_t h, l;
    split_limbs(kern[(size_t)k * N3_ + n], 262144.f, h, l);
    g_w1[idx] = h;
    g_w0[idx] = l;
}

// ---------------------------------------------------------------------------
// IMMA GEMM: acc11 = X1*W1 ; accX = X1*W0 + X0*W1  (s32), fp32 epilogue.
// A[m][k]: k<512 -> x[b,t-1,k] (0 at t==0), else x[b,t,k-512]
// ---------------------------------------------------------------------------
__global__ __launch_bounds__(256, 1)
void gates_gemm_imma(const float* __restrict__ bias)
{
    extern __shared__ char smem[];
    const uint32_t sb = smem_u32(smem);

    const int tid  = threadIdx.x;
    const int wid  = tid >> 5;
    const int lane = tid & 31;
    const int m0 = blockIdx.y * BM;
    const int n0 = blockIdx.x * BN;

    const int wm = (wid >> 2) * 64;      // warp M origin
    const int wn = (wid & 3) * 32;       // warp N origin

    // ---- loader mapping: thread owns row (tid>>1), two 16B segs
    const int arow = tid >> 1;           // 0..127
    const int seg0 = (tid & 1) * 2;      // 0 or 2   (4 segs of 16B per 64B row)
    const int mg = m0 + arow;
    const int tt = mg & (T_ - 1);
    const int avalid = (tt != 0);
    const size_t a_prev = avalid ? (size_t)(mg - 1) * D_ : 0;
    const size_t a_cur  = (size_t)mg * D_;
    const size_t b_off  = (size_t)(n0 + arow) * K_;
    const uint32_t dstRow = (uint32_t)(arow * ROWB);

#define LOAD_STAGE(I) do {                                                    \
        const int s_ = (I) % STAGES;                                          \
        const int kk_ = (I) * BK;                                             \
        const bool fh_ = (kk_ < 512);                                         \
        const int8_t* sx1_; const int8_t* sx0_; int asz_;                     \
        if (fh_) { sx1_ = g_x1 + a_prev + kk_; sx0_ = g_x0 + a_prev + kk_;    \
                   asz_ = avalid ? 16 : 0; }                                  \
        else     { sx1_ = g_x1 + a_cur + kk_ - 512;                           \
                   sx0_ = g_x0 + a_cur + kk_ - 512; asz_ = 16; }              \
        const int8_t* sw1_ = g_w1 + b_off + kk_;                              \
        const int8_t* sw0_ = g_w0 + b_off + kk_;                              \
        const uint32_t d_ = sb + s_ * STAGE_BYTES + dstRow;                   \
        _Pragma("unroll")                                                     \
        for (int j_ = 0; j_ < 2; j_++) {                                      \
            const int sg_ = seg0 + j_;                                        \
            cp16(d_ + 0*MAT_BYTES + sg_*16, sx1_ + sg_*16, asz_);             \
            cp16(d_ + 1*MAT_BYTES + sg_*16, sx0_ + sg_*16, asz_);             \
            cp16(d_ + 2*MAT_BYTES + sg_*16, sw1_ + sg_*16, 16);               \
            cp16(d_ + 3*MAT_BYTES + sg_*16, sw0_ + sg_*16, 16);               \
        }                                                                     \
        asm volatile("cp.async.commit_group;" ::: "memory");                  \
    } while (0)

    // ---- ldmatrix per-lane base byte offsets (within one matrix tile)
    // A: 16-row x 32B kstep tile split into two 16B k-halves
    const uint32_t aRowB = (uint32_t)((wm + (lane & 15)) * ROWB + ((lane >> 4) * 16));
    // B: two n8 tiles x two 16B k-halves
    const uint32_t bRowB = (uint32_t)((wn + ((lane >> 4) & 1) * 8 + (lane & 7)) * ROWB
                                      + (((lane >> 3) & 1) * 16));

    int acc11[4][4][4];
    int accX [4][4][4];
    #pragma unroll
    for (int i = 0; i < 4; i++)
        #pragma unroll
        for (int j = 0; j < 4; j++)
            #pragma unroll
            for (int q = 0; q < 4; q++) { acc11[i][j][q] = 0; accX[i][j][q] = 0; }

    #pragma unroll
    for (int i = 0; i < STAGES - 1; i++) LOAD_STAGE(i);

    for (int i = 0; i < KCHUNKS; i++) {
        asm volatile("cp.async.wait_group %0;" :: "n"(STAGES - 2));
        __syncthreads();

        if (i + STAGES - 1 < KCHUNKS) {
            LOAD_STAGE(i + STAGES - 1);
        } else {
            asm volatile("cp.async.commit_group;" ::: "memory");
        }

        const uint32_t stg = sb + (i % STAGES) * STAGE_BYTES;

        #pragma unroll
        for (int ks = 0; ks < 2; ks++) {
            const uint32_t kb = ks * 32;    // byte offset of k32 step
            uint32_t a1[4][4], a0[4][4], b1[2][4], b0[2][4];
            #pragma unroll
            for (int mi = 0; mi < 4; mi++) {
                ldm_x4(a1[mi], stg + 0*MAT_BYTES + aRowB + mi*16*ROWB + kb);
                ldm_x4(a0[mi], stg + 1*MAT_BYTES + aRowB + mi*16*ROWB + kb);
            }
            #pragma unroll
            for (int np = 0; np < 2; np++) {
                ldm_x4(b1[np], stg + 2*MAT_BYTES + bRowB + np*16*ROWB + kb);
                ldm_x4(b0[np], stg + 3*MAT_BYTES + bRowB + np*16*ROWB + kb);
            }
            #pragma unroll
            for (int mi = 0; mi < 4; mi++) {
                #pragma unroll
                for (int nj = 0; nj < 4; nj++) {
                    const int np = nj >> 1, h = (nj & 1) * 2;
                    imma16832(acc11[mi][nj], a1[mi], b1[np][h], b1[np][h+1]);
                    imma16832(accX [mi][nj], a1[mi], b0[np][h], b0[np][h+1]);
                    imma16832(accX [mi][nj], a0[mi], b1[np][h], b1[np][h+1]);
                }
            }
        }
    }

    // ---- epilogue: gate = acc11*2^-15 + accX*2^-22 + bias; activation
    const bool is_tanh = (n0 < U_);
    const float S11 = 3.0517578125e-5f;      // 2^-15
    const float SX  = 2.384185791015625e-7f; // 2^-22
    #pragma unroll
    for (int nj = 0; nj < 4; nj++) {
        const int c = n0 + wn + nj * 8 + (lane & 3) * 2;
        const float bb0 = __ldg(bias + c);
        const float bb1 = __ldg(bias + c + 1);
        #pragma unroll
        for (int mi = 0; mi < 4; mi++) {
            const int r = m0 + wm + mi * 16 + (lane >> 2);
            float* p0 = g_gates + (size_t)r * N3_ + c;
            float* p1 = g_gates + (size_t)(r + 8) * N3_ + c;
            float2 v0, v1;
            v0.x = fmaf((float)acc11[mi][nj][0], S11, (float)accX[mi][nj][0] * SX) + bb0;
            v0.y = fmaf((float)acc11[mi][nj][1], S11, (float)accX[mi][nj][1] * SX) + bb1;
            v1.x = fmaf((float)acc11[mi][nj][2], S11, (float)accX[mi][nj][2] * SX) + bb0;
            v1.y = fmaf((float)acc11[mi][nj][3], S11, (float)accX[mi][nj][3] * SX) + bb1;
            if (is_tanh) {
                v0.x = tanhf_fast(v0.x); v0.y = tanhf_fast(v0.y);
                v1.x = tanhf_fast(v1.x); v1.y = tanhf_fast(v1.y);
            } else {
                v0.x = sigf(v0.x); v0.y = sigf(v0.y);
                v1.x = sigf(v1.x); v1.y = sigf(v1.y);
            }
            *(float2*)p0 = v0;
            *(float2*)p1 = v1;
        }
    }
#undef LOAD_STAGE
}

// ---------------------------------------------------------------------------
// fo-pool chunked scan (3 passes)
// ---------------------------------------------------------------------------
__global__ __launch_bounds__(256) void scan_pass1()
{
    const int idx   = blockIdx.x * blockDim.x + threadIdx.x;
    const int u     = idx & (U_ - 1);
    const int chunk = (idx >> 9) & (NCHUNK - 1);
    const int b     = idx >> 14;

    size_t base = (size_t)(b * T_ + chunk * TCHUNK) * N3_ + u;
    float c = 0.f, P = 1.f;
    #pragma unroll 4
    for (int s = 0; s < TCHUNK; s++) {
        const float z = g_gates[base];
        const float f = g_gates[base + U_];
        c = fmaf(f, c, (1.f - f) * z);
        P *= f;
        base += N3_;
    }
    g_cend[idx] = c;
    g_P[idx]    = P;
}

__global__ __launch_bounds__(256) void scan_pass2()
{
    const int idx = blockIdx.x * blockDim.x + threadIdx.x;    // 0..4095
    const int u   = idx & (U_ - 1);
    const int b   = idx >> 9;
    float c = 0.f;
    #pragma unroll
    for (int chunk = 0; chunk < NCHUNK; chunk++) {
        const int o = (b * NCHUNK + chunk) * U_ + u;
        g_cst[o] = c;
        c = fmaf(g_P[o], c, g_cend[o]);
    }
}

__global__ __launch_bounds__(256) void scan_pass3(float* __restrict__ out)
{
    const int idx   = blockIdx.x * blockDim.x + threadIdx.x;
    const int u     = idx & (U_ - 1);
    const int chunk = (idx >> 9) & (NCHUNK - 1);
    const int b     = idx >> 14;

    size_t base  = (size_t)(b * T_ + chunk * TCHUNK) * N3_ + u;
    size_t obase = (size_t)(b * T_ + chunk * TCHUNK) * U_ + u;
    float c = g_cst[idx];
    #pragma unroll 4
    for (int s = 0; s < TCHUNK; s++) {
        const float z = g_gates[base];
        const float f = g_gates[base + U_];
        const float o = g_gates[base + 2*U_];
        c = fmaf(f, c, (1.f - f) * z);
        out[obase] = o * c;
        base  += N3_;
        obase += U_;
    }
}

// ---------------------------------------------------------------------------
extern "C" void kernel_launch(void* const* d_in, const int* in_sizes, int n_in,
                              void* d_out, int out_size)
{
    const float* x    = (const float*)d_in[0];
    const float* kern = (const float*)d_in[1];
    const float* bias = (const float*)d_in[2];
    float* out = (float*)d_out;

    cudaFuncSetAttribute(gates_gemm_imma,
                         cudaFuncAttributeMaxDynamicSharedMemorySize, SMEM_TOTAL);

    convert_x<<<(M_ * D_ / 4) / 256, 256>>>(x);
    convert_k<<<(N3_ * K_) / 256, 256>>>(kern);

    dim3 ggrid(N3_ / BN, M_ / BM);   // (12, 256)
    gates_gemm_imma<<<ggrid, 256, SMEM_TOTAL>>>(bias);

    scan_pass1<<<(B_ * NCHUNK * U_) / 256, 256>>>();
    scan_pass2<<<(B_ * U_) / 256, 256>>>();
    scan_pass3<<<(B_ * NCHUNK * U_) / 256, 256>>>(out);
}

// round 5
// speedup vs baseline: 2.6761x; 2.6761x over previous
#include <cuda_runtime.h>
#include <cuda_fp16.h>
#include <stdint.h>
#include <math.h>

// ---------------------------------------------------------------------------
// QRNN on sm_103 (family target; tcgen05 unavailable in this harness).
// gates GEMM (M=32768, N=1536, K=1024) via fp16 mma.sync, 2-product split:
//   x = Xh + Xl (fp16 pair, ~22-bit exact), w = fp16(w) (2^-11 quant)
//   gates = Xh*W + Xl*W   (fp32 accumulate)
// then fo-pool chunked scan.
// ---------------------------------------------------------------------------

#define B_   8
#define T_   4096
#define D_   512
#define U_   512
#define N3_  1536
#define K_   1024
#define M_   (B_*T_)

#define BM 128
#define BN 128
#define BK 32
#define KCHUNKS (K_/BK)          // 32
#define STAGES 4

#define ROWB        80           // 64 data bytes + 16 pad (conflict-free ldmatrix)
#define MAT_BYTES   (128*ROWB)                // 10240
#define STAGE_BYTES (3*MAT_BYTES)             // 30720 (Xh, Xl, W)
#define SMEM_TOTAL  (STAGES*STAGE_BYTES)      // 122880

#define NCHUNK 32
#define TCHUNK (T_/NCHUNK)       // 128

// ---- scratch ----------------------------------------------------------------
__device__ float g_gates[(size_t)M_ * N3_];
__device__ float g_cend [B_*NCHUNK*U_];
__device__ float g_P    [B_*NCHUNK*U_];
__device__ float g_cst  [B_*NCHUNK*U_];
__device__ __half g_xh[(size_t)M_ * D_];
__device__ __half g_xl[(size_t)M_ * D_];
__device__ __half g_wh[(size_t)N3_ * K_];   // transposed [N,K]

// ---- helpers ------------------------------------------------------------------
__device__ __forceinline__ uint32_t smem_u32(const void* p) {
    uint32_t r;
    asm("{ .reg .u64 t; cvta.to.shared.u64 t, %1; cvt.u32.u64 %0, t; }" : "=r"(r) : "l"(p));
    return r;
}
__device__ __forceinline__ void cp16(uint32_t dst, const void* src, int ssize) {
    asm volatile("cp.async.cg.shared.global [%0], [%1], 16, %2;"
                 :: "r"(dst), "l"(src), "r"(ssize) : "memory");
}
__device__ __forceinline__ void ldm_x4(uint32_t* r, uint32_t addr) {
    asm volatile("ldmatrix.sync.aligned.m8n8.x4.shared.b16 {%0,%1,%2,%3}, [%4];"
                 : "=r"(r[0]), "=r"(r[1]), "=r"(r[2]), "=r"(r[3]) : "r"(addr));
}
__device__ __forceinline__ void mma16816(float* d, const uint32_t* a,
                                         uint32_t b0, uint32_t b1) {
    asm volatile(
        "mma.sync.aligned.m16n8k16.row.col.f32.f16.f16.f32 "
        "{%0,%1,%2,%3},{%4,%5,%6,%7},{%8,%9},{%0,%1,%2,%3};"
        : "+f"(d[0]), "+f"(d[1]), "+f"(d[2]), "+f"(d[3])
        : "r"(a[0]), "r"(a[1]), "r"(a[2]), "r"(a[3]), "r"(b0), "r"(b1));
}
__device__ __forceinline__ float sigf(float x) {
    float e = __expf(-x);
    float d = 1.f + e, r;
    asm("rcp.approx.f32 %0, %1;" : "=f"(r) : "f"(d));
    return r;
}
__device__ __forceinline__ float tanhf_fast(float x) {
    return 2.f * sigf(2.f * x) - 1.f;
}

// ---------------------------------------------------------------------------
// converters
// ---------------------------------------------------------------------------
__global__ __launch_bounds__(256) void convert_x(const float* __restrict__ x) {
    size_t i = ((size_t)blockIdx.x * blockDim.x + threadIdx.x) * 4;
    float4 v = *(const float4*)(x + i);
    float vv[4] = {v.x, v.y, v.z, v.w};
    __half h[4], l[4];
    #pragma unroll
    for (int j = 0; j < 4; j++) {
        h[j] = __float2half_rn(vv[j]);
        l[j] = __float2half_rn(vv[j] - __half2float(h[j]));
    }
    *(uint2*)(g_xh + i) = *(uint2*)h;
    *(uint2*)(g_xl + i) = *(uint2*)l;
}

__global__ __launch_bounds__(256) void convert_k(const float* __restrict__ kern) {
    int idx = blockIdx.x * blockDim.x + threadIdx.x;   // over N3_*K_
    int n = idx >> 10;
    int k = idx & (K_ - 1);
    g_wh[idx] = __float2half_rn(kern[(size_t)k * N3_ + n]);
}

// ---------------------------------------------------------------------------
// HMMA GEMM: gates = Xh*W + Xl*W  (fp32 accum), + bias + activation.
// A[m][k]: k<512 -> x[b,t-1,k] (0 at t==0), else x[b,t,k-512]
// smem per stage: 3 matrices (Xh, Xl, W) of [128][BK] fp16, ROWB pitch.
// ---------------------------------------------------------------------------
__global__ __launch_bounds__(256, 1)
void gates_gemm_hmma(const float* __restrict__ bias)
{
    extern __shared__ char smem[];
    const uint32_t sb = smem_u32(smem);

    const int tid  = threadIdx.x;
    const int wid  = tid >> 5;
    const int lane = tid & 31;
    const int m0 = blockIdx.y * BM;
    const int n0 = blockIdx.x * BN;

    const int wm = (wid >> 2) * 64;      // warp M origin
    const int wn = (wid & 3) * 32;       // warp N origin

    // ---- loader mapping: thread owns row (tid>>1), two 16B segs
    const int arow = tid >> 1;           // 0..127
    const int seg0 = (tid & 1) * 2;      // 0 or 2
    const int mg = m0 + arow;
    const int tt = mg & (T_ - 1);
    const int avalid = (tt != 0);
    const size_t a_prev = avalid ? (size_t)(mg - 1) * D_ : 0;
    const size_t a_cur  = (size_t)mg * D_;
    const size_t b_off  = (size_t)(n0 + arow) * K_;
    const uint32_t dstRow = (uint32_t)(arow * ROWB);

#define LOAD_STAGE(I) do {                                                    \
        const int s_ = (I) % STAGES;                                          \
        const int kk_ = (I) * BK;                                             \
        const bool fh_ = (kk_ < 512);                                         \
        const __half* sxh_; const __half* sxl_; int asz_;                     \
        if (fh_) { sxh_ = g_xh + a_prev + kk_; sxl_ = g_xl + a_prev + kk_;    \
                   asz_ = avalid ? 16 : 0; }                                  \
        else     { sxh_ = g_xh + a_cur + kk_ - 512;                           \
                   sxl_ = g_xl + a_cur + kk_ - 512; asz_ = 16; }              \
        const __half* sw_ = g_wh + b_off + kk_;                               \
        const uint32_t d_ = sb + s_ * STAGE_BYTES + dstRow;                   \
        _Pragma("unroll")                                                     \
        for (int j_ = 0; j_ < 2; j_++) {                                      \
            const int sg_ = seg0 + j_;                                        \
            cp16(d_ + 0*MAT_BYTES + sg_*16, sxh_ + sg_*8, asz_);              \
            cp16(d_ + 1*MAT_BYTES + sg_*16, sxl_ + sg_*8, asz_);              \
            cp16(d_ + 2*MAT_BYTES + sg_*16, sw_  + sg_*8, 16);                \
        }                                                                     \
        asm volatile("cp.async.commit_group;" ::: "memory");                  \
    } while (0)

    // ---- ldmatrix per-lane base byte offsets (within one matrix tile)
    const uint32_t aRowB = (uint32_t)((wm + (lane & 15)) * ROWB + ((lane >> 4) * 16));
    const uint32_t bRowB = (uint32_t)((wn + ((lane >> 4) & 1) * 8 + (lane & 7)) * ROWB
                                      + (((lane >> 3) & 1) * 16));

    float acc[4][4][4];
    #pragma unroll
    for (int i = 0; i < 4; i++)
        #pragma unroll
        for (int j = 0; j < 4; j++)
            #pragma unroll
            for (int q = 0; q < 4; q++) acc[i][j][q] = 0.f;

    #pragma unroll
    for (int i = 0; i < STAGES - 1; i++) LOAD_STAGE(i);

    for (int i = 0; i < KCHUNKS; i++) {
        asm volatile("cp.async.wait_group %0;" :: "n"(STAGES - 2));
        __syncthreads();

        if (i + STAGES - 1 < KCHUNKS) {
            LOAD_STAGE(i + STAGES - 1);
        } else {
            asm volatile("cp.async.commit_group;" ::: "memory");
        }

        const uint32_t stg = sb + (i % STAGES) * STAGE_BYTES;

        #pragma unroll
        for (int ks = 0; ks < 2; ks++) {
            const uint32_t kb = ks * 32;    // byte offset of k16 step
            uint32_t ah[4][4], al[4][4], bw[2][4];
            #pragma unroll
            for (int mi = 0; mi < 4; mi++) {
                ldm_x4(ah[mi], stg + 0*MAT_BYTES + aRowB + mi*16*ROWB + kb);
                ldm_x4(al[mi], stg + 1*MAT_BYTES + aRowB + mi*16*ROWB + kb);
            }
            #pragma unroll
            for (int np = 0; np < 2; np++) {
                ldm_x4(bw[np], stg + 2*MAT_BYTES + bRowB + np*16*ROWB + kb);
            }
            #pragma unroll
            for (int mi = 0; mi < 4; mi++) {
                #pragma unroll
                for (int nj = 0; nj < 4; nj++) {
                    const int np = nj >> 1, h = (nj & 1) * 2;
                    mma16816(acc[mi][nj], ah[mi], bw[np][h], bw[np][h+1]);
                    mma16816(acc[mi][nj], al[mi], bw[np][h], bw[np][h+1]);
                }
            }
        }
    }

    // ---- epilogue: bias + activation -> g_gates (f32)
    const bool is_tanh = (n0 < U_);
    #pragma unroll
    for (int nj = 0; nj < 4; nj++) {
        const int c = n0 + wn + nj * 8 + (lane & 3) * 2;
        const float bb0 = __ldg(bias + c);
        const float bb1 = __ldg(bias + c + 1);
        #pragma unroll
        for (int mi = 0; mi < 4; mi++) {
            const int r = m0 + wm + mi * 16 + (lane >> 2);
            float* p0 = g_gates + (size_t)r * N3_ + c;
            float* p1 = g_gates + (size_t)(r + 8) * N3_ + c;
            float2 v0, v1;
            v0.x = acc[mi][nj][0] + bb0; v0.y = acc[mi][nj][1] + bb1;
            v1.x = acc[mi][nj][2] + bb0; v1.y = acc[mi][nj][3] + bb1;
            if (is_tanh) {
                v0.x = tanhf_fast(v0.x); v0.y = tanhf_fast(v0.y);
                v1.x = tanhf_fast(v1.x); v1.y = tanhf_fast(v1.y);
            } else {
                v0.x = sigf(v0.x); v0.y = sigf(v0.y);
                v1.x = sigf(v1.x); v1.y = sigf(v1.y);
            }
            *(float2*)p0 = v0;
            *(float2*)p1 = v1;
        }
    }
#undef LOAD_STAGE
}

// ---------------------------------------------------------------------------
// fo-pool chunked scan (3 passes)
// ---------------------------------------------------------------------------
__global__ __launch_bounds__(256) void scan_pass1()
{
    const int idx   = blockIdx.x * blockDim.x + threadIdx.x;
    const int u     = idx & (U_ - 1);
    const int chunk = (idx >> 9) & (NCHUNK - 1);
    const int b     = idx >> 14;

    size_t base = (size_t)(b * T_ + chunk * TCHUNK) * N3_ + u;
    float c = 0.f, P = 1.f;
    #pragma unroll 4
    for (int s = 0; s < TCHUNK; s++) {
        const float z = g_gates[base];
        const float f = g_gates[base + U_];
        c = fmaf(f, c, (1.f - f) * z);
        P *= f;
        base += N3_;
    }
    g_cend[idx] = c;
    g_P[idx]    = P;
}

__global__ __launch_bounds__(256) void scan_pass2()
{
    const int idx = blockIdx.x * blockDim.x + threadIdx.x;    // 0..4095
    const int u   = idx & (U_ - 1);
    const int b   = idx >> 9;
    float c = 0.f;
    #pragma unroll
    for (int chunk = 0; chunk < NCHUNK; chunk++) {
        const int o = (b * NCHUNK + chunk) * U_ + u;
        g_cst[o] = c;
        c = fmaf(g_P[o], c, g_cend[o]);
    }
}

__global__ __launch_bounds__(256) void scan_pass3(float* __restrict__ out)
{
    const int idx   = blockIdx.x * blockDim.x + threadIdx.x;
    const int u     = idx & (U_ - 1);
    const int chunk = (idx >> 9) & (NCHUNK - 1);
    const int b     = idx >> 14;

    size_t base  = (size_t)(b * T_ + chunk * TCHUNK) * N3_ + u;
    size_t obase = (size_t)(b * T_ + chunk * TCHUNK) * U_ + u;
    float c = g_cst[idx];
    #pragma unroll 4
    for (int s = 0; s < TCHUNK; s++) {
        const float z = g_gates[base];
        const float f = g_gates[base + U_];
        const float o = g_gates[base + 2*U_];
        c = fmaf(f, c, (1.f - f) * z);
        out[obase] = o * c;
        base  += N3_;
        obase += U_;
    }
}

// ---------------------------------------------------------------------------
extern "C" void kernel_launch(void* const* d_in, const int* in_sizes, int n_in,
                              void* d_out, int out_size)
{
    const float* x    = (const float*)d_in[0];
    const float* kern = (const float*)d_in[1];
    const float* bias = (const float*)d_in[2];
    float* out = (float*)d_out;

    cudaFuncSetAttribute(gates_gemm_hmma,
                         cudaFuncAttributeMaxDynamicSharedMemorySize, SMEM_TOTAL);

    convert_x<<<(M_ * D_ / 4) / 256, 256>>>(x);
    convert_k<<<(N3_ * K_) / 256, 256>>>(kern);

    dim3 ggrid(N3_ / BN, M_ / BM);   // (12, 256)
    gates_gemm_hmma<<<ggrid, 256, SMEM_TOTAL>>>(bias);

    scan_pass1<<<(B_ * NCHUNK * U_) / 256, 256>>>();
    scan_pass2<<<(B_ * U_) / 256, 256>>>();
    scan_pass3<<<(B_ * NCHUNK * U_) / 256, 256>>>(out);
}

// round 6
// speedup vs baseline: 4.6913x; 1.7530x over previous
#include <cuda_runtime.h>
#include <cuda_fp16.h>
#include <stdint.h>
#include <math.h>

// ---------------------------------------------------------------------------
// QRNN on sm_103 (family target; tcgen05 unavailable in this harness).
// gates GEMM (M=32768, N=1536, K=1024) via single-product fp16 mma.sync:
//   gates = fp16(x) * fp16(w)  (fp32 accumulate)  -- err ~3.5e-4 << 1e-3
// then fo-pool chunked scan.
// ---------------------------------------------------------------------------

#define B_   8
#define T_   4096
#define D_   512
#define U_   512
#define N3_  1536
#define K_   1024
#define M_   (B_*T_)

#define BM 128
#define BN 128
#define BK 32
#define KCHUNKS (K_/BK)          // 32
#define STAGES 4

#define ROWB        80           // 64 data bytes + 16 pad (conflict-free ldmatrix)
#define MAT_BYTES   (128*ROWB)                // 10240
#define STAGE_BYTES (2*MAT_BYTES)             // 20480 (X, W)
#define SMEM_TOTAL  (STAGES*STAGE_BYTES)      // 81920

#define NCHUNK 32
#define TCHUNK (T_/NCHUNK)       // 128

// ---- scratch ----------------------------------------------------------------
__device__ float g_gates[(size_t)M_ * N3_];
__device__ float g_cend [B_*NCHUNK*U_];
__device__ float g_P    [B_*NCHUNK*U_];
__device__ float g_cst  [B_*NCHUNK*U_];
__device__ __half g_xh[(size_t)M_ * D_];
__device__ __half g_wh[(size_t)N3_ * K_];   // transposed [N,K]

// ---- helpers ------------------------------------------------------------------
__device__ __forceinline__ uint32_t smem_u32(const void* p) {
    uint32_t r;
    asm("{ .reg .u64 t; cvta.to.shared.u64 t, %1; cvt.u32.u64 %0, t; }" : "=r"(r) : "l"(p));
    return r;
}
__device__ __forceinline__ void cp16(uint32_t dst, const void* src, int ssize) {
    asm volatile("cp.async.cg.shared.global [%0], [%1], 16, %2;"
                 :: "r"(dst), "l"(src), "r"(ssize) : "memory");
}
__device__ __forceinline__ void ldm_x4(uint32_t* r, uint32_t addr) {
    asm volatile("ldmatrix.sync.aligned.m8n8.x4.shared.b16 {%0,%1,%2,%3}, [%4];"
                 : "=r"(r[0]), "=r"(r[1]), "=r"(r[2]), "=r"(r[3]) : "r"(addr));
}
__device__ __forceinline__ void mma16816(float* d, const uint32_t* a,
                                         uint32_t b0, uint32_t b1) {
    asm volatile(
        "mma.sync.aligned.m16n8k16.row.col.f32.f16.f16.f32 "
        "{%0,%1,%2,%3},{%4,%5,%6,%7},{%8,%9},{%0,%1,%2,%3};"
        : "+f"(d[0]), "+f"(d[1]), "+f"(d[2]), "+f"(d[3])
        : "r"(a[0]), "r"(a[1]), "r"(a[2]), "r"(a[3]), "r"(b0), "r"(b1));
}
__device__ __forceinline__ float sigf(float x) {
    float e = __expf(-x);
    float d = 1.f + e, r;
    asm("rcp.approx.f32 %0, %1;" : "=f"(r) : "f"(d));
    return r;
}
__device__ __forceinline__ float tanhf_fast(float x) {
    return 2.f * sigf(2.f * x) - 1.f;
}

// ---------------------------------------------------------------------------
// converters
// ---------------------------------------------------------------------------
__global__ __launch_bounds__(256) void convert_x(const float* __restrict__ x) {
    size_t i = ((size_t)blockIdx.x * blockDim.x + threadIdx.x) * 4;
    float4 v = *(const float4*)(x + i);
    __half2 h0 = __floats2half2_rn(v.x, v.y);
    __half2 h1 = __floats2half2_rn(v.z, v.w);
    *(uint2*)(g_xh + i) = make_uint2(*(uint32_t*)&h0, *(uint32_t*)&h1);
}

__global__ __launch_bounds__(256) void convert_k(const float* __restrict__ kern) {
    int idx = blockIdx.x * blockDim.x + threadIdx.x;   // over N3_*K_
    int n = idx >> 10;
    int k = idx & (K_ - 1);
    g_wh[idx] = __float2half_rn(kern[(size_t)k * N3_ + n]);
}

// ---------------------------------------------------------------------------
// HMMA GEMM: gates = X*W (fp32 accum), + bias + activation.
// A[m][k]: k<512 -> x[b,t-1,k] (0 at t==0), else x[b,t,k-512]
// smem per stage: 2 matrices (X, W) of [128][BK] fp16, ROWB pitch.
// ---------------------------------------------------------------------------
__global__ __launch_bounds__(256)
void gates_gemm_hmma(const float* __restrict__ bias)
{
    extern __shared__ char smem[];
    const uint32_t sb = smem_u32(smem);

    const int tid  = threadIdx.x;
    const int wid  = tid >> 5;
    const int lane = tid & 31;
    const int m0 = blockIdx.y * BM;
    const int n0 = blockIdx.x * BN;

    const int wm = (wid >> 2) * 64;      // warp M origin
    const int wn = (wid & 3) * 32;       // warp N origin

    // ---- loader mapping: thread owns row (tid>>1), two 16B segs
    const int arow = tid >> 1;           // 0..127
    const int seg0 = (tid & 1) * 2;      // 0 or 2
    const int mg = m0 + arow;
    const int tt = mg & (T_ - 1);
    const int avalid = (tt != 0);
    const size_t a_prev = avalid ? (size_t)(mg - 1) * D_ : 0;
    const size_t a_cur  = (size_t)mg * D_;
    const size_t b_off  = (size_t)(n0 + arow) * K_;
    const uint32_t dstRow = (uint32_t)(arow * ROWB);

#define LOAD_STAGE(I) do {                                                    \
        const int s_ = (I) % STAGES;                                          \
        const int kk_ = (I) * BK;                                             \
        const bool fh_ = (kk_ < 512);                                         \
        const __half* sx_; int asz_;                                          \
        if (fh_) { sx_ = g_xh + a_prev + kk_; asz_ = avalid ? 16 : 0; }       \
        else     { sx_ = g_xh + a_cur + kk_ - 512; asz_ = 16; }               \
        const __half* sw_ = g_wh + b_off + kk_;                               \
        const uint32_t d_ = sb + s_ * STAGE_BYTES + dstRow;                   \
        _Pragma("unroll")                                                     \
        for (int j_ = 0; j_ < 2; j_++) {                                      \
            const int sg_ = seg0 + j_;                                        \
            cp16(d_ + 0*MAT_BYTES + sg_*16, sx_ + sg_*8, asz_);               \
            cp16(d_ + 1*MAT_BYTES + sg_*16, sw_ + sg_*8, 16);                 \
        }                                                                     \
        asm volatile("cp.async.commit_group;" ::: "memory");                  \
    } while (0)

    // ---- ldmatrix per-lane base byte offsets (within one matrix tile)
    const uint32_t aRowB = (uint32_t)((wm + (lane & 15)) * ROWB + ((lane >> 4) * 16));
    const uint32_t bRowB = (uint32_t)((wn + ((lane >> 4) & 1) * 8 + (lane & 7)) * ROWB
                                      + (((lane >> 3) & 1) * 16));

    float acc[4][4][4];
    #pragma unroll
    for (int i = 0; i < 4; i++)
        #pragma unroll
        for (int j = 0; j < 4; j++)
            #pragma unroll
            for (int q = 0; q < 4; q++) acc[i][j][q] = 0.f;

    #pragma unroll
    for (int i = 0; i < STAGES - 1; i++) LOAD_STAGE(i);

    for (int i = 0; i < KCHUNKS; i++) {
        asm volatile("cp.async.wait_group %0;" :: "n"(STAGES - 2));
        __syncthreads();

        if (i + STAGES - 1 < KCHUNKS) {
            LOAD_STAGE(i + STAGES - 1);
        } else {
            asm volatile("cp.async.commit_group;" ::: "memory");
        }

        const uint32_t stg = sb + (i % STAGES) * STAGE_BYTES;

        #pragma unroll
        for (int ks = 0; ks < 2; ks++) {
            const uint32_t kb = ks * 32;    // byte offset of k16 step
            uint32_t ax[4][4], bw[2][4];
            #pragma unroll
            for (int mi = 0; mi < 4; mi++) {
                ldm_x4(ax[mi], stg + 0*MAT_BYTES + aRowB + mi*16*ROWB + kb);
            }
            #pragma unroll
            for (int np = 0; np < 2; np++) {
                ldm_x4(bw[np], stg + 1*MAT_BYTES + bRowB + np*16*ROWB + kb);
            }
            #pragma unroll
            for (int mi = 0; mi < 4; mi++) {
                #pragma unroll
                for (int nj = 0; nj < 4; nj++) {
                    const int np = nj >> 1, h = (nj & 1) * 2;
                    mma16816(acc[mi][nj], ax[mi], bw[np][h], bw[np][h+1]);
                }
            }
        }
    }

    // ---- epilogue: bias + activation -> g_gates (f32)
    const bool is_tanh = (n0 < U_);
    #pragma unroll
    for (int nj = 0; nj < 4; nj++) {
        const int c = n0 + wn + nj * 8 + (lane & 3) * 2;
        const float bb0 = __ldg(bias + c);
        const float bb1 = __ldg(bias + c + 1);
        #pragma unroll
        for (int mi = 0; mi < 4; mi++) {
            const int r = m0 + wm + mi * 16 + (lane >> 2);
            float* p0 = g_gates + (size_t)r * N3_ + c;
            float* p1 = g_gates + (size_t)(r + 8) * N3_ + c;
            float2 v0, v1;
            v0.x = acc[mi][nj][0] + bb0; v0.y = acc[mi][nj][1] + bb1;
            v1.x = acc[mi][nj][2] + bb0; v1.y = acc[mi][nj][3] + bb1;
            if (is_tanh) {
                v0.x = tanhf_fast(v0.x); v0.y = tanhf_fast(v0.y);
                v1.x = tanhf_fast(v1.x); v1.y = tanhf_fast(v1.y);
            } else {
                v0.x = sigf(v0.x); v0.y = sigf(v0.y);
                v1.x = sigf(v1.x); v1.y = sigf(v1.y);
            }
            *(float2*)p0 = v0;
            *(float2*)p1 = v1;
        }
    }
#undef LOAD_STAGE
}

// ---------------------------------------------------------------------------
// fo-pool chunked scan (3 passes)
// ---------------------------------------------------------------------------
__global__ __launch_bounds__(256) void scan_pass1()
{
    const int idx   = blockIdx.x * blockDim.x + threadIdx.x;
    const int u     = idx & (U_ - 1);
    const int chunk = (idx >> 9) & (NCHUNK - 1);
    const int b     = idx >> 14;

    size_t base = (size_t)(b * T_ + chunk * TCHUNK) * N3_ + u;
    float c = 0.f, P = 1.f;
    #pragma unroll 4
    for (int s = 0; s < TCHUNK; s++) {
        const float z = g_gates[base];
        const float f = g_gates[base + U_];
        c = fmaf(f, c, (1.f - f) * z);
        P *= f;
        base += N3_;
    }
    g_cend[idx] = c;
    g_P[idx]    = P;
}

__global__ __launch_bounds__(256) void scan_pass2()
{
    const int idx = blockIdx.x * blockDim.x + threadIdx.x;    // 0..4095
    const int u   = idx & (U_ - 1);
    const int b   = idx >> 9;
    float c = 0.f;
    #pragma unroll
    for (int chunk = 0; chunk < NCHUNK; chunk++) {
        const int o = (b * NCHUNK + chunk) * U_ + u;
        g_cst[o] = c;
        c = fmaf(g_P[o], c, g_cend[o]);
    }
}

__global__ __launch_bounds__(256) void scan_pass3(float* __restrict__ out)
{
    const int idx   = blockIdx.x * blockDim.x + threadIdx.x;
    const int u     = idx & (U_ - 1);
    const int chunk = (idx >> 9) & (NCHUNK - 1);
    const int b     = idx >> 14;

    size_t base  = (size_t)(b * T_ + chunk * TCHUNK) * N3_ + u;
    size_t obase = (size_t)(b * T_ + chunk * TCHUNK) * U_ + u;
    float c = g_cst[idx];
    #pragma unroll 4
    for (int s = 0; s < TCHUNK; s++) {
        const float z = g_gates[base];
        const float f = g_gates[base + U_];
        const float o = g_gates[base + 2*U_];
        c = fmaf(f, c, (1.f - f) * z);
        out[obase] = o * c;
        base  += N3_;
        obase += U_;
    }
}

// ---------------------------------------------------------------------------
extern "C" void kernel_launch(void* const* d_in, const int* in_sizes, int n_in,
                              void* d_out, int out_size)
{
    const float* x    = (const float*)d_in[0];
    const float* kern = (const float*)d_in[1];
    const float* bias = (const float*)d_in[2];
    float* out = (float*)d_out;

    cudaFuncSetAttribute(gates_gemm_hmma,
                         cudaFuncAttributeMaxDynamicSharedMemorySize, SMEM_TOTAL);

    convert_x<<<(M_ * D_ / 4) / 256, 256>>>(x);
    convert_k<<<(N3_ * K_) / 256, 256>>>(kern);

    dim3 ggrid(N3_ / BN, M_ / BM);   // (12, 256)
    gates_gemm_hmma<<<ggrid, 256, SMEM_TOTAL>>>(bias);

    scan_pass1<<<(B_ * NCHUNK * U_) / 256, 256>>>();
    scan_pass2<<<(B_ * U_) / 256, 256>>>();
    scan_pass3<<<(B_ * NCHUNK * U_) / 256, 256>>>(out);
}

// round 7
// speedup vs baseline: 5.0677x; 1.0802x over previous
#include <cuda_runtime.h>
#include <cuda_fp16.h>
#include <stdint.h>
#include <math.h>

// ---------------------------------------------------------------------------
// QRNN on sm_103 (family target; tcgen05 unavailable in this harness).
// gates GEMM (M=32768, N=1536, K=1024) single-product fp16 mma.sync,
// gates stored fp16; fo-pool chunked scan on half2 lanes.
// ---------------------------------------------------------------------------

#define B_   8
#define T_   4096
#define D_   512
#define U_   512
#define N3_  1536
#define K_   1024
#define M_   (B_*T_)

#define BM 128
#define BN 128
#define BK 32
#define KCHUNKS (K_/BK)          // 32
#define STAGES 4

#define ROWB        80           // 64 data bytes + 16 pad (conflict-free ldmatrix)
#define MAT_BYTES   (128*ROWB)                // 10240
#define STAGE_BYTES (2*MAT_BYTES)             // 20480 (X, W)
#define SMEM_TOTAL  (STAGES*STAGE_BYTES)      // 81920

#define NCHUNK 64
#define TCHUNK (T_/NCHUNK)       // 64
#define U2 (U_/2)                // 256 half2 lanes per gate region
#define N3H2 (N3_/2)             // 768 half2 per row

// ---- scratch ----------------------------------------------------------------
__device__ __half g_gatesh[(size_t)M_ * N3_];        // 96 MB, z|f|o fp16
__device__ float g_cend [B_*NCHUNK*U_];
__device__ float g_P    [B_*NCHUNK*U_];
__device__ float g_cst  [B_*NCHUNK*U_];
__device__ __half g_xh[(size_t)M_ * D_];
__device__ __half g_wh[(size_t)N3_ * K_];            // transposed [N,K]

// ---- helpers ------------------------------------------------------------------
__device__ __forceinline__ uint32_t smem_u32(const void* p) {
    uint32_t r;
    asm("{ .reg .u64 t; cvta.to.shared.u64 t, %1; cvt.u32.u64 %0, t; }" : "=r"(r) : "l"(p));
    return r;
}
__device__ __forceinline__ void cp16(uint32_t dst, const void* src, int ssize) {
    asm volatile("cp.async.cg.shared.global [%0], [%1], 16, %2;"
                 :: "r"(dst), "l"(src), "r"(ssize) : "memory");
}
__device__ __forceinline__ void ldm_x4(uint32_t* r, uint32_t addr) {
    asm volatile("ldmatrix.sync.aligned.m8n8.x4.shared.b16 {%0,%1,%2,%3}, [%4];"
                 : "=r"(r[0]), "=r"(r[1]), "=r"(r[2]), "=r"(r[3]) : "r"(addr));
}
__device__ __forceinline__ void mma16816(float* d, const uint32_t* a,
                                         uint32_t b0, uint32_t b1) {
    asm volatile(
        "mma.sync.aligned.m16n8k16.row.col.f32.f16.f16.f32 "
        "{%0,%1,%2,%3},{%4,%5,%6,%7},{%8,%9},{%0,%1,%2,%3};"
        : "+f"(d[0]), "+f"(d[1]), "+f"(d[2]), "+f"(d[3])
        : "r"(a[0]), "r"(a[1]), "r"(a[2]), "r"(a[3]), "r"(b0), "r"(b1));
}
__device__ __forceinline__ float sigf(float x) {
    float e = __expf(-x);
    float d = 1.f + e, r;
    asm("rcp.approx.f32 %0, %1;" : "=f"(r) : "f"(d));
    return r;
}
__device__ __forceinline__ float tanhf_fast(float x) {
    return 2.f * sigf(2.f * x) - 1.f;
}

// ---------------------------------------------------------------------------
// converters
// ---------------------------------------------------------------------------
__global__ __launch_bounds__(256) void convert_x(const float* __restrict__ x) {
    size_t i = ((size_t)blockIdx.x * blockDim.x + threadIdx.x) * 4;
    float4 v = *(const float4*)(x + i);
    __half2 h0 = __floats2half2_rn(v.x, v.y);
    __half2 h1 = __floats2half2_rn(v.z, v.w);
    *(uint2*)(g_xh + i) = make_uint2(*(uint32_t*)&h0, *(uint32_t*)&h1);
}

__global__ __launch_bounds__(256) void convert_k(const float* __restrict__ kern) {
    int idx = blockIdx.x * blockDim.x + threadIdx.x;   // over N3_*K_
    int n = idx >> 10;
    int k = idx & (K_ - 1);
    g_wh[idx] = __float2half_rn(kern[(size_t)k * N3_ + n]);
}

// ---------------------------------------------------------------------------
// HMMA GEMM: gates = X*W (fp32 accum), + bias + activation -> fp16 store.
// A[m][k]: k<512 -> x[b,t-1,k] (0 at t==0), else x[b,t,k-512]
// ---------------------------------------------------------------------------
__global__ __launch_bounds__(256, 2)
void gates_gemm_hmma(const float* __restrict__ bias)
{
    extern __shared__ char smem[];
    const uint32_t sb = smem_u32(smem);

    const int tid  = threadIdx.x;
    const int wid  = tid >> 5;
    const int lane = tid & 31;
    const int m0 = blockIdx.y * BM;
    const int n0 = blockIdx.x * BN;

    const int wm = (wid >> 2) * 64;      // warp M origin
    const int wn = (wid & 3) * 32;       // warp N origin

    // ---- loader mapping: thread owns row (tid>>1), two 16B segs
    const int arow = tid >> 1;           // 0..127
    const int seg0 = (tid & 1) * 2;      // 0 or 2
    const int mg = m0 + arow;
    const int tt = mg & (T_ - 1);
    const int avalid = (tt != 0);
    const size_t a_prev = avalid ? (size_t)(mg - 1) * D_ : 0;
    const size_t a_cur  = (size_t)mg * D_;
    const size_t b_off  = (size_t)(n0 + arow) * K_;
    const uint32_t dstRow = (uint32_t)(arow * ROWB);

#define LOAD_STAGE(I) do {                                                    \
        const int s_ = (I) % STAGES;                                          \
        const int kk_ = (I) * BK;                                             \
        const bool fh_ = (kk_ < 512);                                         \
        const __half* sx_; int asz_;                                          \
        if (fh_) { sx_ = g_xh + a_prev + kk_; asz_ = avalid ? 16 : 0; }       \
        else     { sx_ = g_xh + a_cur + kk_ - 512; asz_ = 16; }               \
        const __half* sw_ = g_wh + b_off + kk_;                               \
        const uint32_t d_ = sb + s_ * STAGE_BYTES + dstRow;                   \
        _Pragma("unroll")                                                     \
        for (int j_ = 0; j_ < 2; j_++) {                                      \
            const int sg_ = seg0 + j_;                                        \
            cp16(d_ + 0*MAT_BYTES + sg_*16, sx_ + sg_*8, asz_);               \
            cp16(d_ + 1*MAT_BYTES + sg_*16, sw_ + sg_*8, 16);                 \
        }                                                                     \
        asm volatile("cp.async.commit_group;" ::: "memory");                  \
    } while (0)

    // ---- ldmatrix per-lane base byte offsets (within one matrix tile)
    const uint32_t aRowB = (uint32_t)((wm + (lane & 15)) * ROWB + ((lane >> 4) * 16));
    const uint32_t bRowB = (uint32_t)((wn + ((lane >> 4) & 1) * 8 + (lane & 7)) * ROWB
                                      + (((lane >> 3) & 1) * 16));

    float acc[4][4][4];
    #pragma unroll
    for (int i = 0; i < 4; i++)
        #pragma unroll
        for (int j = 0; j < 4; j++)
            #pragma unroll
            for (int q = 0; q < 4; q++) acc[i][j][q] = 0.f;

    #pragma unroll
    for (int i = 0; i < STAGES - 1; i++) LOAD_STAGE(i);

    for (int i = 0; i < KCHUNKS; i++) {
        asm volatile("cp.async.wait_group %0;" :: "n"(STAGES - 2));
        __syncthreads();

        if (i + STAGES - 1 < KCHUNKS) {
            LOAD_STAGE(i + STAGES - 1);
        } else {
            asm volatile("cp.async.commit_group;" ::: "memory");
        }

        const uint32_t stg = sb + (i % STAGES) * STAGE_BYTES;

        #pragma unroll
        for (int ks = 0; ks < 2; ks++) {
            const uint32_t kb = ks * 32;    // byte offset of k16 step
            uint32_t ax[4][4], bw[2][4];
            #pragma unroll
            for (int mi = 0; mi < 4; mi++) {
                ldm_x4(ax[mi], stg + 0*MAT_BYTES + aRowB + mi*16*ROWB + kb);
            }
            #pragma unroll
            for (int np = 0; np < 2; np++) {
                ldm_x4(bw[np], stg + 1*MAT_BYTES + bRowB + np*16*ROWB + kb);
            }
            #pragma unroll
            for (int mi = 0; mi < 4; mi++) {
                #pragma unroll
                for (int nj = 0; nj < 4; nj++) {
                    const int np = nj >> 1, h = (nj & 1) * 2;
                    mma16816(acc[mi][nj], ax[mi], bw[np][h], bw[np][h+1]);
                }
            }
        }
    }

    // ---- epilogue: bias + activation -> g_gatesh (fp16)
    const bool is_tanh = (n0 < U_);
    #pragma unroll
    for (int nj = 0; nj < 4; nj++) {
        const int c = n0 + wn + nj * 8 + (lane & 3) * 2;
        const float bb0 = __ldg(bias + c);
        const float bb1 = __ldg(bias + c + 1);
        #pragma unroll
        for (int mi = 0; mi < 4; mi++) {
            const int r = m0 + wm + mi * 16 + (lane >> 2);
            float2 v0, v1;
            v0.x = acc[mi][nj][0] + bb0; v0.y = acc[mi][nj][1] + bb1;
            v1.x = acc[mi][nj][2] + bb0; v1.y = acc[mi][nj][3] + bb1;
            if (is_tanh) {
                v0.x = tanhf_fast(v0.x); v0.y = tanhf_fast(v0.y);
                v1.x = tanhf_fast(v1.x); v1.y = tanhf_fast(v1.y);
            } else {
                v0.x = sigf(v0.x); v0.y = sigf(v0.y);
                v1.x = sigf(v1.x); v1.y = sigf(v1.y);
            }
            __half2 h0 = __floats2half2_rn(v0.x, v0.y);
            __half2 h1 = __floats2half2_rn(v1.x, v1.y);
            *(__half2*)(g_gatesh + (size_t)r * N3_ + c)       = h0;
            *(__half2*)(g_gatesh + (size_t)(r + 8) * N3_ + c) = h1;
        }
    }
#undef LOAD_STAGE
}

// ---------------------------------------------------------------------------
// fo-pool chunked scan (3 passes), half2 lanes (each thread owns 2 units)
// ---------------------------------------------------------------------------
__global__ __launch_bounds__(256) void scan_pass1()
{
    const int idx   = blockIdx.x * blockDim.x + threadIdx.x;  // b*(64*256)+chunk*256+u2
    const int u2    = idx & (U2 - 1);
    const int chunk = (idx >> 8) & (NCHUNK - 1);
    const int b     = idx >> 14;

    const __half2* gh = (const __half2*)g_gatesh;
    size_t base = (size_t)(b * T_ + chunk * TCHUNK) * N3H2 + u2;
    float2 c = make_float2(0.f, 0.f);
    float2 P = make_float2(1.f, 1.f);
    #pragma unroll 8
    for (int s = 0; s < TCHUNK; s++) {
        const float2 z = __half22float2(gh[base]);
        const float2 f = __half22float2(gh[base + U2]);
        c.x = fmaf(f.x, c.x, (1.f - f.x) * z.x);
        c.y = fmaf(f.y, c.y, (1.f - f.y) * z.y);
        P.x *= f.x; P.y *= f.y;
        base += N3H2;
    }
    const int o = ((b * NCHUNK + chunk) * U2 + u2) * 2;
    *(float2*)(g_cend + o) = c;
    *(float2*)(g_P + o)    = P;
}

__global__ __launch_bounds__(256) void scan_pass2()
{
    const int idx = blockIdx.x * blockDim.x + threadIdx.x;    // 0..4095
    const int u   = idx & (U_ - 1);
    const int b   = idx >> 9;
    float c = 0.f;
    #pragma unroll
    for (int chunk = 0; chunk < NCHUNK; chunk++) {
        const int o = (b * NCHUNK + chunk) * U_ + u;
        g_cst[o] = c;
        c = fmaf(g_P[o], c, g_cend[o]);
    }
}

__global__ __launch_bounds__(256) void scan_pass3(float* __restrict__ out)
{
    const int idx   = blockIdx.x * blockDim.x + threadIdx.x;
    const int u2    = idx & (U2 - 1);
    const int chunk = (idx >> 8) & (NCHUNK - 1);
    const int b     = idx >> 14;

    const __half2* gh = (const __half2*)g_gatesh;
    size_t base  = (size_t)(b * T_ + chunk * TCHUNK) * N3H2 + u2;
    size_t obase = (size_t)(b * T_ + chunk * TCHUNK) * U_ + u2 * 2;
    float2 c = *(const float2*)(g_cst + ((b * NCHUNK + chunk) * U2 + u2) * 2);
    #pragma unroll 4
    for (int s = 0; s < TCHUNK; s++) {
        const float2 z = __half22float2(gh[base]);
        const float2 f = __half22float2(gh[base + U2]);
        const float2 o = __half22float2(gh[base + 2 * U2]);
        c.x = fmaf(f.x, c.x, (1.f - f.x) * z.x);
        c.y = fmaf(f.y, c.y, (1.f - f.y) * z.y);
        float2 y;
        y.x = o.x * c.x;
        y.y = o.y * c.y;
        *(float2*)(out + obase) = y;
        base  += N3H2;
        obase += U_;
    }
}

// ---------------------------------------------------------------------------
extern "C" void kernel_launch(void* const* d_in, const int* in_sizes, int n_in,
                              void* d_out, int out_size)
{
    const float* x    = (const float*)d_in[0];
    const float* kern = (const float*)d_in[1];
    const float* bias = (const float*)d_in[2];
    float* out = (float*)d_out;

    cudaFuncSetAttribute(gates_gemm_hmma,
                         cudaFuncAttributeMaxDynamicSharedMemorySize, SMEM_TOTAL);

    convert_x<<<(M_ * D_ / 4) / 256, 256>>>(x);
    convert_k<<<(N3_ * K_) / 256, 256>>>(kern);

    dim3 ggrid(N3_ / BN, M_ / BM);   // (12, 256)
    gates_gemm_hmma<<<ggrid, 256, SMEM_TOTAL>>>(bias);

    scan_pass1<<<(B_ * NCHUNK * U2) / 256, 256>>>();
    scan_pass2<<<(B_ * U_) / 256, 256>>>();
    scan_pass3<<<(B_ * NCHUNK * U2) / 256, 256>>>(out);
}